// round 1
// baseline (speedup 1.0000x reference)
#include <cuda_runtime.h>
#include <cstdint>

#define NN 21
#define D 256
#define GH 512
#define NE 40
#define NB 8192
#define M_TOTAL (NB * NN)     /* 172032 */
#define NCAT 1280             /* 256 (V) + 512 (A=src part) + 512 (B=dst part) */
#define LN_EPS 1e-5f

#define MT 128
#define NT 128
#define KT 16

// ---------------- scratch (static device memory; no allocations) ----------------
__device__ float g_xln[(size_t)M_TOTAL * D];
__device__ float g_Y[(size_t)M_TOTAL * NCAT];
__device__ float g_Wcat[(size_t)D * NCAT];
__device__ float g_bias[NCAT];

// ---------------- helpers ----------------
__device__ __forceinline__ void cp_async16(void* smem, const void* gmem) {
    unsigned s = (unsigned)__cvta_generic_to_shared(smem);
    asm volatile("cp.async.cg.shared.global [%0], [%1], 16;\n" :: "r"(s), "l"(gmem));
}

__device__ __forceinline__ unsigned f2tf(float x) {
    unsigned r;
    asm("cvt.rna.tf32.f32 %0, %1;" : "=r"(r) : "f"(x));
    return r;
}

__device__ __forceinline__ void mma8(float* d, const unsigned* a, const unsigned* b) {
    asm volatile(
        "mma.sync.aligned.m16n8k8.row.col.f32.tf32.tf32.f32 "
        "{%0,%1,%2,%3}, {%4,%5,%6,%7}, {%8,%9}, {%0,%1,%2,%3};\n"
        : "+f"(d[0]), "+f"(d[1]), "+f"(d[2]), "+f"(d[3])
        : "r"(a[0]), "r"(a[1]), "r"(a[2]), "r"(a[3]), "r"(b[0]), "r"(b[1]));
}

// ---------------- kernel 0: build concatenated weight + bias ----------------
__global__ void prep_kernel(const float* __restrict__ Wv, const float* __restrict__ bv,
                            const float* __restrict__ W1, const float* __restrict__ b1) {
    int idx = blockIdx.x * blockDim.x + threadIdx.x;
    if (idx < D * NCAT) {
        int k = idx / NCAT, n = idx % NCAT;
        float w;
        if (n < 256)      w = Wv[k * 256 + n];
        else if (n < 768) w = W1[k * 512 + (n - 256)];
        else              w = W1[(256 + k) * 512 + (n - 768)];
        g_Wcat[idx] = w;
    }
    if (idx < NCAT) {
        g_bias[idx] = (idx < 256) ? bv[idx] : (idx < 768 ? b1[idx - 256] : 0.f);
    }
}

// ---------------- kernel 1: LayerNorm ----------------
__global__ void ln_kernel(const float* __restrict__ h, const float* __restrict__ w,
                          const float* __restrict__ b) {
    int row = blockIdx.x;
    int tid = threadIdx.x;
    float v = h[(size_t)row * D + tid];
    __shared__ float s1[8], s2[8];
    float a = v, q = v * v;
    #pragma unroll
    for (int off = 16; off; off >>= 1) {
        a += __shfl_xor_sync(0xffffffffu, a, off);
        q += __shfl_xor_sync(0xffffffffu, q, off);
    }
    int warp = tid >> 5, lane = tid & 31;
    if (!lane) { s1[warp] = a; s2[warp] = q; }
    __syncthreads();
    if (tid == 0) {
        float ta = 0.f, tq = 0.f;
        #pragma unroll
        for (int i = 0; i < 8; i++) { ta += s1[i]; tq += s2[i]; }
        s1[0] = ta; s2[0] = tq;
    }
    __syncthreads();
    float mu  = s1[0] * (1.f / D);
    float var = s2[0] * (1.f / D) - mu * mu;
    float inv = rsqrtf(var + LN_EPS);
    g_xln[(size_t)row * D + tid] = (v - mu) * inv * w[tid] + b[tid];
}

// ---------------- kernel 2: tf32 GEMM  Y[M,1280] = xln[M,256] @ Wcat + bias ----------------
__device__ __forceinline__ void load_tiles(int tid, int mBase, int nBase, int kt,
                                           float (*As)[20], float (*Bs)[136]) {
    #pragma unroll
    for (int i = 0; i < 2; i++) {           // A: 128 rows x 16 cols = 512 x 16B chunks
        int ch = tid + i * 256;
        int r = ch >> 2, c4 = (ch & 3) * 4;
        cp_async16(&As[r][c4], g_xln + (size_t)(mBase + r) * D + kt * KT + c4);
    }
    #pragma unroll
    for (int i = 0; i < 2; i++) {           // B: 16 rows x 128 cols = 512 x 16B chunks
        int ch = tid + i * 256;
        int r = ch >> 5, c4 = (ch & 31) * 4;
        cp_async16(&Bs[r][c4], g_Wcat + (size_t)(kt * KT + r) * NCAT + nBase + c4);
    }
    asm volatile("cp.async.commit_group;\n");
}

__device__ __forceinline__ void compute_tile(int lane, int wm, int wn,
                                             const float (*As)[20], const float (*Bs)[136],
                                             float c[4][4][4]) {
    #pragma unroll
    for (int ks = 0; ks < 2; ks++) {
        const int k0 = ks * 8;
        unsigned af[4][4], bf[4][2];
        #pragma unroll
        for (int mi = 0; mi < 4; mi++) {
            int rb = wm * 64 + mi * 16 + (lane >> 2);
            int cc = k0 + (lane & 3);
            af[mi][0] = f2tf(As[rb][cc]);
            af[mi][1] = f2tf(As[rb + 8][cc]);
            af[mi][2] = f2tf(As[rb][cc + 4]);
            af[mi][3] = f2tf(As[rb + 8][cc + 4]);
        }
        #pragma unroll
        for (int ni = 0; ni < 4; ni++) {
            int cb = wn * 32 + ni * 8 + (lane >> 2);
            int rr = k0 + (lane & 3);
            bf[ni][0] = f2tf(Bs[rr][cb]);
            bf[ni][1] = f2tf(Bs[rr + 4][cb]);
        }
        #pragma unroll
        for (int mi = 0; mi < 4; mi++)
            #pragma unroll
            for (int ni = 0; ni < 4; ni++)
                mma8(c[mi][ni], af[mi], bf[ni]);
    }
}

__global__ __launch_bounds__(256) void gemm_kernel() {
    __shared__ float As[2][MT][20];
    __shared__ float Bs[2][KT][136];
    int tid = threadIdx.x;
    int mBase = blockIdx.y * MT;
    int nBase = blockIdx.x * NT;
    int warp = tid >> 5, lane = tid & 31;
    int wm = warp & 1, wn = warp >> 1;   // 2 x 4 warp grid, warp tile 64x32

    float c[4][4][4];
    #pragma unroll
    for (int mi = 0; mi < 4; mi++)
        #pragma unroll
        for (int ni = 0; ni < 4; ni++)
            #pragma unroll
            for (int j = 0; j < 4; j++) c[mi][ni][j] = 0.f;

    const int KTILES = D / KT;  // 16
    load_tiles(tid, mBase, nBase, 0, As[0], Bs[0]);
    for (int kt = 0; kt < KTILES; kt++) {
        int buf = kt & 1;
        if (kt + 1 < KTILES) {
            load_tiles(tid, mBase, nBase, kt + 1, As[buf ^ 1], Bs[buf ^ 1]);
            asm volatile("cp.async.wait_group 1;\n");
        } else {
            asm volatile("cp.async.wait_group 0;\n");
        }
        __syncthreads();
        compute_tile(lane, wm, wn, As[buf], Bs[buf], c);
        __syncthreads();
    }

    // epilogue: add bias, store
    #pragma unroll
    for (int mi = 0; mi < 4; mi++)
        #pragma unroll
        for (int ni = 0; ni < 4; ni++) {
            int r0 = mBase + wm * 64 + mi * 16 + (lane >> 2);
            int c0 = nBase + wn * 32 + ni * 8 + (lane & 3) * 2;
            float b0v = g_bias[c0], b1v = g_bias[c0 + 1];
            g_Y[(size_t)r0 * NCAT + c0]           = c[mi][ni][0] + b0v;
            g_Y[(size_t)r0 * NCAT + c0 + 1]       = c[mi][ni][1] + b1v;
            g_Y[(size_t)(r0 + 8) * NCAT + c0]     = c[mi][ni][2] + b0v;
            g_Y[(size_t)(r0 + 8) * NCAT + c0 + 1] = c[mi][ni][3] + b1v;
        }
}

// ---------------- kernel 3: gates + scatter-aggregate + residual ----------------
__global__ __launch_bounds__(256) void edge_kernel(const float* __restrict__ h,
                                                   const int* __restrict__ srcI,
                                                   const int* __restrict__ dstI,
                                                   const float* __restrict__ W2,
                                                   const float* __restrict__ b2,
                                                   float* __restrict__ out) {
    __shared__ float sV[NN * D];
    __shared__ float sGate[NE];
    __shared__ int sSrc[NE], sDst[NE];
    __shared__ float sW2[GH];
    int b = blockIdx.x;
    int tid = threadIdx.x;
    if (tid < NE) { sSrc[tid] = srcI[tid]; sDst[tid] = dstI[tid]; }
    for (int i = tid; i < GH; i += 256) sW2[i] = W2[i];
    const float* Yb = g_Y + (size_t)b * NN * NCAT;
    for (int i = tid; i < NN * D; i += 256) {
        int n = i >> 8, dc = i & 255;
        sV[i] = Yb[n * NCAT + dc];          // V part (bv already added)
    }
    __syncthreads();

    int warp = tid >> 5, lane = tid & 31;
    float b2v = b2[0];
    for (int e = warp; e < NE; e += 8) {
        int s = sSrc[e], dn = sDst[e];
        const float* Ar = Yb + s * NCAT + 256;   // src@W1_top + b1
        const float* Br = Yb + dn * NCAT + 768;  // dst@W1_bot
        float sum = 0.f;
        for (int hh = lane; hh < GH; hh += 32) {
            float t = Ar[hh] + Br[hh];
            float ge = 0.5f * t * (1.f + erff(t * 0.7071067811865476f));
            sum += ge * sW2[hh];
        }
        #pragma unroll
        for (int off = 16; off; off >>= 1) sum += __shfl_xor_sync(0xffffffffu, sum, off);
        if (!lane) sGate[e] = 1.f / (1.f + expf(-(sum + b2v)));
    }
    __syncthreads();

    const float* hb = h + (size_t)b * NN * D;
    float* ob = out + (size_t)b * NN * D;
    #pragma unroll 1
    for (int n = 0; n < NN; n++) {
        float acc = hb[n * D + tid];
        #pragma unroll 1
        for (int e = 0; e < NE; e++) {
            if (sDst[e] == n) acc += sGate[e] * sV[sSrc[e] * D + tid];
        }
        ob[n * D + tid] = acc;
    }
}

// ---------------- launcher ----------------
extern "C" void kernel_launch(void* const* d_in, const int* in_sizes, int n_in,
                              void* d_out, int out_size) {
    const float* h    = (const float*)d_in[0];
    const int*   srcI = (const int*)d_in[1];
    const int*   dstI = (const int*)d_in[2];
    const float* ln_w = (const float*)d_in[3];
    const float* ln_b = (const float*)d_in[4];
    const float* Wv   = (const float*)d_in[5];
    const float* bv   = (const float*)d_in[6];
    const float* W1   = (const float*)d_in[7];
    const float* b1   = (const float*)d_in[8];
    const float* W2   = (const float*)d_in[9];
    const float* b2   = (const float*)d_in[10];
    float* out = (float*)d_out;

    prep_kernel<<<(D * NCAT + 255) / 256, 256>>>(Wv, bv, W1, b1);
    ln_kernel<<<M_TOTAL, 256>>>(h, ln_w, ln_b);
    dim3 ggrid(NCAT / NT, M_TOTAL / MT);   // (10, 1344)
    gemm_kernel<<<ggrid, 256>>>();
    edge_kernel<<<NB, 256>>>(h, srcI, dstI, W2, b2, out);
}

// round 3
// speedup vs baseline: 1.7545x; 1.7545x over previous
#include <cuda_runtime.h>
#include <cstdint>

#define NN 21
#define D 256
#define GH 512
#define NE 40
#define NB 8192
#define M_TOTAL (NB * NN)     /* 172032 */
#define NCAT 1280
#define LN_EPS 1e-5f

#define MT 128
#define NTC 256               /* N chunk */
#define NCHUNK (NCAT / NTC)   /* 5 */
#define KT 16
#define KSTEPS (D / KT)       /* 16 */

#define A_STRIDE 260          /* 260 % 32 == 4 -> banks 4r+k, conflict-free */
#define B_STRIDE 264          /* 264 % 32 == 8 -> banks 8r+c, conflict-free */
#define A_SMEM_FLOATS (MT * A_STRIDE)              /* 33280 */
#define B_SMEM_FLOATS (3 * KT * B_STRIDE)          /* 12672 */
#define GEMM_SMEM_BYTES ((A_SMEM_FLOATS + B_SMEM_FLOATS) * 4)

// ---------------- scratch ----------------
__device__ float g_xln[(size_t)M_TOTAL * D];
__device__ float g_Y[(size_t)M_TOTAL * NCAT];
__device__ float g_Wcat[(size_t)D * NCAT];
__device__ float g_bias[NCAT];
__device__ int   g_bStart[NN + 1];
__device__ int   g_bEdge[NE];

// ---------------- helpers ----------------
__device__ __forceinline__ void cp_async16(void* smem, const void* gmem) {
    unsigned s = (unsigned)__cvta_generic_to_shared(smem);
    asm volatile("cp.async.cg.shared.global [%0], [%1], 16;\n" :: "r"(s), "l"(gmem));
}
__device__ __forceinline__ unsigned f2tf(float x) {
    unsigned r; asm("cvt.rna.tf32.f32 %0, %1;" : "=r"(r) : "f"(x)); return r;
}
__device__ __forceinline__ void mma8(float* d, const unsigned* a, const unsigned* b) {
    asm volatile(
        "mma.sync.aligned.m16n8k8.row.col.f32.tf32.tf32.f32 "
        "{%0,%1,%2,%3}, {%4,%5,%6,%7}, {%8,%9}, {%0,%1,%2,%3};\n"
        : "+f"(d[0]), "+f"(d[1]), "+f"(d[2]), "+f"(d[3])
        : "r"(a[0]), "r"(a[1]), "r"(a[2]), "r"(a[3]), "r"(b[0]), "r"(b[1]));
}
__device__ __forceinline__ float gelu1(float t) {
    return 0.5f * t * (1.f + erff(t * 0.7071067811865476f));
}

// ---------------- kernel 0: weights concat + bias + edge buckets ----------------
__global__ void prep_kernel(const float* __restrict__ Wv, const float* __restrict__ bv,
                            const float* __restrict__ W1, const float* __restrict__ b1,
                            const int* __restrict__ srcI, const int* __restrict__ dstI) {
    int idx = blockIdx.x * blockDim.x + threadIdx.x;
    if (idx < D * NCAT) {
        int k = idx / NCAT, n = idx % NCAT;
        float w;
        if (n < 256)      w = Wv[k * 256 + n];
        else if (n < 768) w = W1[k * 512 + (n - 256)];
        else              w = W1[(256 + k) * 512 + (n - 768)];
        g_Wcat[idx] = w;
    }
    if (idx < NCAT)
        g_bias[idx] = (idx < 256) ? bv[idx] : (idx < 768 ? b1[idx - 256] : 0.f);
    if (blockIdx.x == 0 && threadIdx.x == 0) {
        int cnt[NN];
        for (int n = 0; n < NN; n++) cnt[n] = 0;
        for (int e = 0; e < NE; e++) cnt[dstI[e]]++;
        g_bStart[0] = 0;
        for (int n = 0; n < NN; n++) g_bStart[n + 1] = g_bStart[n] + cnt[n];
        int pos[NN];
        for (int n = 0; n < NN; n++) pos[n] = g_bStart[n];
        for (int e = 0; e < NE; e++) g_bEdge[pos[dstI[e]]++] = e;
    }
}

// ---------------- kernel 1: LayerNorm (warp per row, float4) ----------------
__global__ __launch_bounds__(256) void ln_kernel(const float* __restrict__ h,
                                                 const float* __restrict__ w,
                                                 const float* __restrict__ b) {
    int row  = blockIdx.x * 8 + (threadIdx.x >> 5);
    int lane = threadIdx.x & 31;
    const float4* r4 = (const float4*)(h + (size_t)row * D);
    float4 v0 = r4[lane], v1 = r4[lane + 32];
    float s  = v0.x + v0.y + v0.z + v0.w + v1.x + v1.y + v1.z + v1.w;
    float q  = v0.x*v0.x + v0.y*v0.y + v0.z*v0.z + v0.w*v0.w
             + v1.x*v1.x + v1.y*v1.y + v1.z*v1.z + v1.w*v1.w;
    #pragma unroll
    for (int off = 16; off; off >>= 1) {
        s += __shfl_xor_sync(0xffffffffu, s, off);
        q += __shfl_xor_sync(0xffffffffu, q, off);
    }
    float mu  = s * (1.f / D);
    float var = q * (1.f / D) - mu * mu;
    float inv = rsqrtf(var + LN_EPS);
    float4 w0 = ((const float4*)w)[lane], w1 = ((const float4*)w)[lane + 32];
    float4 b0 = ((const float4*)b)[lane], b1 = ((const float4*)b)[lane + 32];
    float4 o0, o1;
    o0.x = (v0.x - mu) * inv * w0.x + b0.x;  o0.y = (v0.y - mu) * inv * w0.y + b0.y;
    o0.z = (v0.z - mu) * inv * w0.z + b0.z;  o0.w = (v0.w - mu) * inv * w0.w + b0.w;
    o1.x = (v1.x - mu) * inv * w1.x + b1.x;  o1.y = (v1.y - mu) * inv * w1.y + b1.y;
    o1.z = (v1.z - mu) * inv * w1.z + b1.z;  o1.w = (v1.w - mu) * inv * w1.w + b1.w;
    float4* out4 = (float4*)(g_xln + (size_t)row * D);
    out4[lane] = o0; out4[lane + 32] = o1;
}

// ---------------- kernel 2: tf32 GEMM, A-resident, loop over N chunks ----------------
__device__ __forceinline__ void load_B_stage(float* Bs, int tid, int nBase, int kt) {
    // 16 rows x 256 cols = 1024 float4 chunks, 4 per thread
    #pragma unroll
    for (int i = 0; i < 4; i++) {
        int ch = tid + i * 256;
        int r = ch >> 6, c = (ch & 63) * 4;
        cp_async16(Bs + r * B_STRIDE + c,
                   g_Wcat + (size_t)(kt * KT + r) * NCAT + nBase + c);
    }
    asm volatile("cp.async.commit_group;\n");
}

__global__ __launch_bounds__(256, 1) void gemm_kernel() {
    extern __shared__ float smem[];
    float* As = smem;                    // [MT][A_STRIDE]
    float* Bs = smem + A_SMEM_FLOATS;    // [3][KT][B_STRIDE]
    int tid  = threadIdx.x;
    int mBase = blockIdx.x * MT;
    int warp = tid >> 5, lane = tid & 31;
    int wm = warp & 1, wn = warp >> 1;   // warp tile 64 x 64

    // load full A tile (128 x 256) once
    #pragma unroll
    for (int i = 0; i < 32; i++) {
        int ch = tid + i * 256;          // 8192 chunks
        int r = ch >> 6, c = (ch & 63) * 4;
        cp_async16(As + r * A_STRIDE + c, g_xln + (size_t)(mBase + r) * D + c);
    }
    asm volatile("cp.async.commit_group;\n");

    for (int nc = 0; nc < NCHUNK; nc++) {
        int nBase = nc * NTC;
        float c[4][8][4];
        #pragma unroll
        for (int mi = 0; mi < 4; mi++)
            #pragma unroll
            for (int ni = 0; ni < 8; ni++)
                #pragma unroll
                for (int j = 0; j < 4; j++) c[mi][ni][j] = 0.f;

        __syncthreads();  // previous chunk's compute done before overwriting Bs
        load_B_stage(Bs + 0 * KT * B_STRIDE, tid, nBase, 0);
        load_B_stage(Bs + 1 * KT * B_STRIDE, tid, nBase, 1);

        for (int kt = 0; kt < KSTEPS; kt++) {
            if (kt < KSTEPS - 1) asm volatile("cp.async.wait_group 1;\n");
            else                 asm volatile("cp.async.wait_group 0;\n");
            __syncthreads();
            if (kt + 2 < KSTEPS)
                load_B_stage(Bs + ((kt + 2) % 3) * KT * B_STRIDE, tid, nBase, kt + 2);
            const float* Bst = Bs + (kt % 3) * KT * B_STRIDE;
            #pragma unroll
            for (int ks = 0; ks < 2; ks++) {
                const int k0 = ks * 8;
                unsigned af[4][4], bf[8][2];
                #pragma unroll
                for (int mi = 0; mi < 4; mi++) {
                    int rb = wm * 64 + mi * 16 + (lane >> 2);
                    int cc = kt * KT + k0 + (lane & 3);   // FIX: advance A columns with kt
                    af[mi][0] = f2tf(As[rb * A_STRIDE + cc]);
                    af[mi][1] = f2tf(As[(rb + 8) * A_STRIDE + cc]);
                    af[mi][2] = f2tf(As[rb * A_STRIDE + cc + 4]);
                    af[mi][3] = f2tf(As[(rb + 8) * A_STRIDE + cc + 4]);
                }
                #pragma unroll
                for (int ni = 0; ni < 8; ni++) {
                    int cb = wn * 64 + ni * 8 + (lane >> 2);
                    int rr = k0 + (lane & 3);
                    bf[ni][0] = f2tf(Bst[rr * B_STRIDE + cb]);
                    bf[ni][1] = f2tf(Bst[(rr + 4) * B_STRIDE + cb]);
                }
                #pragma unroll
                for (int mi = 0; mi < 4; mi++)
                    #pragma unroll
                    for (int ni = 0; ni < 8; ni++)
                        mma8(c[mi][ni], af[mi], bf[ni]);
            }
        }

        // epilogue: bias + store (float2)
        #pragma unroll
        for (int mi = 0; mi < 4; mi++)
            #pragma unroll
            for (int ni = 0; ni < 8; ni++) {
                int r0 = mBase + wm * 64 + mi * 16 + (lane >> 2);
                int c0 = nBase + wn * 64 + ni * 8 + (lane & 3) * 2;
                float b0v = g_bias[c0], b1v = g_bias[c0 + 1];
                float2 v0 = make_float2(c[mi][ni][0] + b0v, c[mi][ni][1] + b1v);
                float2 v1 = make_float2(c[mi][ni][2] + b0v, c[mi][ni][3] + b1v);
                *(float2*)(g_Y + (size_t)r0 * NCAT + c0)       = v0;
                *(float2*)(g_Y + (size_t)(r0 + 8) * NCAT + c0) = v1;
            }
    }
}

// ---------------- kernel 3: gates + bucketed scatter + residual ----------------
__global__ __launch_bounds__(256) void edge_kernel(const float* __restrict__ h,
                                                   const int* __restrict__ srcI,
                                                   const int* __restrict__ dstI,
                                                   const float* __restrict__ W2,
                                                   const float* __restrict__ b2,
                                                   float* __restrict__ out) {
    __shared__ float4 sV4[NN * 64];        // V part, 21 x 256 floats
    __shared__ float  sGate[NE];
    __shared__ float4 sW2[128];            // 512 floats
    __shared__ int sSrc[NE], sBS[NN + 1], sBE[NE];
    int b = blockIdx.x;
    int tid = threadIdx.x;
    if (tid < NE) { sSrc[tid] = srcI[tid]; sBE[tid] = g_bEdge[tid]; }
    if (tid >= 64 && tid < 64 + NN + 1) sBS[tid - 64] = g_bStart[tid - 64];
    if (tid >= 128 && tid < 256) sW2[tid - 128] = ((const float4*)W2)[tid - 128];
    const float* Yb = g_Y + (size_t)b * NN * NCAT;
    for (int i = tid; i < NN * 64; i += 256) {
        int n = i >> 6, c = i & 63;
        sV4[i] = ((const float4*)(Yb + n * NCAT))[c];
    }
    __syncthreads();

    int warp = tid >> 5, lane = tid & 31;
    float b2v = b2[0];
    for (int e = warp; e < NE; e += 8) {
        int s = sSrc[e], dn = dstI[e];
        const float4* A4 = (const float4*)(Yb + s * NCAT + 256);
        const float4* B4 = (const float4*)(Yb + dn * NCAT + 768);
        float sum = 0.f;
        #pragma unroll
        for (int i = lane; i < 128; i += 32) {
            float4 a = __ldg(A4 + i), bb = __ldg(B4 + i), w = sW2[i];
            sum += gelu1(a.x + bb.x) * w.x;
            sum += gelu1(a.y + bb.y) * w.y;
            sum += gelu1(a.z + bb.z) * w.z;
            sum += gelu1(a.w + bb.w) * w.w;
        }
        #pragma unroll
        for (int off = 16; off; off >>= 1) sum += __shfl_xor_sync(0xffffffffu, sum, off);
        if (!lane) sGate[e] = 1.f / (1.f + __expf(-(sum + b2v)));
    }
    __syncthreads();

    const float* hb = h + (size_t)b * NN * D;
    float* ob = out + (size_t)b * NN * D;
    int col = tid & 63, sub = tid >> 6;    // 4 nodes at a time, 64 float4-lanes each
    for (int n0 = 0; n0 < 24; n0 += 4) {
        int n = n0 + sub;
        if (n < NN) {
            float4 acc = ((const float4*)(hb + n * D))[col];
            int jEnd = sBS[n + 1];
            for (int j = sBS[n]; j < jEnd; j++) {
                int e = sBE[j];
                float g = sGate[e];
                float4 v = sV4[sSrc[e] * 64 + col];
                acc.x += g * v.x; acc.y += g * v.y;
                acc.z += g * v.z; acc.w += g * v.w;
            }
            ((float4*)(ob + n * D))[col] = acc;
        }
    }
}

// ---------------- launcher ----------------
extern "C" void kernel_launch(void* const* d_in, const int* in_sizes, int n_in,
                              void* d_out, int out_size) {
    const float* h    = (const float*)d_in[0];
    const int*   srcI = (const int*)d_in[1];
    const int*   dstI = (const int*)d_in[2];
    const float* ln_w = (const float*)d_in[3];
    const float* ln_b = (const float*)d_in[4];
    const float* Wv   = (const float*)d_in[5];
    const float* bv   = (const float*)d_in[6];
    const float* W1   = (const float*)d_in[7];
    const float* b1   = (const float*)d_in[8];
    const float* W2   = (const float*)d_in[9];
    const float* b2   = (const float*)d_in[10];
    float* out = (float*)d_out;

    cudaFuncSetAttribute(gemm_kernel, cudaFuncAttributeMaxDynamicSharedMemorySize,
                         GEMM_SMEM_BYTES);

    prep_kernel<<<(D * NCAT + 255) / 256, 256>>>(Wv, bv, W1, b1, srcI, dstI);
    ln_kernel<<<M_TOTAL / 8, 256>>>(h, ln_w, ln_b);
    gemm_kernel<<<M_TOTAL / MT, 256, GEMM_SMEM_BYTES>>>();
    edge_kernel<<<NB, 256>>>(h, srcI, dstI, W2, b2, out);
}

// round 5
// speedup vs baseline: 2.6194x; 1.4929x over previous
#include <cuda_runtime.h>
#include <cuda_fp16.h>
#include <cstdint>

#define NN 21
#define D 256
#define GH 512
#define NE 40
#define NB 8192
#define M_TOTAL (NB * NN)     /* 172032 */
#define NCAT 1280
#define LN_EPS 1e-5f

#define MT 128                /* M per CTA */
#define NTC 256               /* N chunk (4 warps x 64) */
#define NNC (NCAT / NTC)      /* 5 */
#define KC 32                 /* K per B stage */
#define KCS (D / KC)          /* 8 */
#define NITER (NNC * KCS)     /* 40 */

#define A_STRH 264            /* halves; 528B/row -> bank shift 4/row */
#define B_STRH 40             /* halves; 80B/row  -> bank shift 20/row */
#define SM_A_BYTES (MT * A_STRH * 2)            /* 67584 */
#define SM_B_STAGE (NTC * B_STRH * 2)           /* 20480 */
#define GEMM_SMEM (SM_A_BYTES + 3 * SM_B_STAGE) /* 129024 */

// ---------------- scratch ----------------
__device__ __half g_xln[(size_t)M_TOTAL * D];
__device__ __half g_Y[(size_t)M_TOTAL * NCAT];
__device__ __half g_WcatT[(size_t)NCAT * D];   /* [n][k] K-major */
__device__ float  g_bias[NCAT];
__device__ int    g_bStart[NN + 1];
__device__ int    g_bEdge[NE];

// ---------------- helpers ----------------
__device__ __forceinline__ void cp_async16(void* smem, const void* gmem) {
    unsigned s = (unsigned)__cvta_generic_to_shared(smem);
    asm volatile("cp.async.cg.shared.global [%0], [%1], 16;\n" :: "r"(s), "l"(gmem));
}
__device__ __forceinline__ float gelu1(float t) {
    return 0.5f * t * (1.f + erff(t * 0.7071067811865476f));
}
__device__ __forceinline__ void mma16(float* d, const unsigned* a, const unsigned* b) {
    asm volatile(
        "mma.sync.aligned.m16n8k16.row.col.f32.f16.f16.f32 "
        "{%0,%1,%2,%3}, {%4,%5,%6,%7}, {%8,%9}, {%0,%1,%2,%3};\n"
        : "+f"(d[0]), "+f"(d[1]), "+f"(d[2]), "+f"(d[3])
        : "r"(a[0]), "r"(a[1]), "r"(a[2]), "r"(a[3]), "r"(b[0]), "r"(b[1]));
}

// ---------------- kernel 0: weights (transposed fp16) + bias + edge buckets ----------------
__global__ void prep_kernel(const float* __restrict__ Wv, const float* __restrict__ bv,
                            const float* __restrict__ W1, const float* __restrict__ b1,
                            const int* __restrict__ srcI, const int* __restrict__ dstI) {
    int idx = blockIdx.x * blockDim.x + threadIdx.x;
    if (idx < D * NCAT) {
        int k = idx / NCAT, n = idx % NCAT;
        float w;
        if (n < 256)      w = Wv[k * 256 + n];
        else if (n < 768) w = W1[k * 512 + (n - 256)];
        else              w = W1[(256 + k) * 512 + (n - 768)];
        g_WcatT[(size_t)n * D + k] = __float2half_rn(w);
    }
    if (idx < NCAT)
        g_bias[idx] = (idx < 256) ? bv[idx] : (idx < 768 ? b1[idx - 256] : 0.f);
    if (blockIdx.x == 0 && threadIdx.x == 0) {
        int cnt[NN];
        for (int n = 0; n < NN; n++) cnt[n] = 0;
        for (int e = 0; e < NE; e++) cnt[dstI[e]]++;
        g_bStart[0] = 0;
        for (int n = 0; n < NN; n++) g_bStart[n + 1] = g_bStart[n] + cnt[n];
        int pos[NN];
        for (int n = 0; n < NN; n++) pos[n] = g_bStart[n];
        for (int e = 0; e < NE; e++) g_bEdge[pos[dstI[e]]++] = e;
    }
}

// ---------------- kernel 1: LayerNorm (warp/row, fp16 out) ----------------
__global__ __launch_bounds__(256) void ln_kernel(const float* __restrict__ h,
                                                 const float* __restrict__ w,
                                                 const float* __restrict__ b) {
    int row  = blockIdx.x * 8 + (threadIdx.x >> 5);
    int lane = threadIdx.x & 31;
    const float4* r4 = (const float4*)(h + (size_t)row * D);
    float4 va = r4[2 * lane], vb = r4[2 * lane + 1];
    float s  = va.x + va.y + va.z + va.w + vb.x + vb.y + vb.z + vb.w;
    float q  = va.x*va.x + va.y*va.y + va.z*va.z + va.w*va.w
             + vb.x*vb.x + vb.y*vb.y + vb.z*vb.z + vb.w*vb.w;
    #pragma unroll
    for (int off = 16; off; off >>= 1) {
        s += __shfl_xor_sync(0xffffffffu, s, off);
        q += __shfl_xor_sync(0xffffffffu, q, off);
    }
    float mu  = s * (1.f / D);
    float var = q * (1.f / D) - mu * mu;
    float inv = rsqrtf(var + LN_EPS);
    float4 w0 = ((const float4*)w)[2 * lane], w1 = ((const float4*)w)[2 * lane + 1];
    float4 b0 = ((const float4*)b)[2 * lane], b1 = ((const float4*)b)[2 * lane + 1];
    __half2 h0 = __floats2half2_rn((va.x - mu) * inv * w0.x + b0.x,
                                   (va.y - mu) * inv * w0.y + b0.y);
    __half2 h1 = __floats2half2_rn((va.z - mu) * inv * w0.z + b0.z,
                                   (va.w - mu) * inv * w0.w + b0.w);
    __half2 h2 = __floats2half2_rn((vb.x - mu) * inv * w1.x + b1.x,
                                   (vb.y - mu) * inv * w1.y + b1.y);
    __half2 h3 = __floats2half2_rn((vb.z - mu) * inv * w1.z + b1.z,
                                   (vb.w - mu) * inv * w1.w + b1.w);
    uint4 o;
    o.x = *(unsigned*)&h0; o.y = *(unsigned*)&h1;
    o.z = *(unsigned*)&h2; o.w = *(unsigned*)&h3;
    ((uint4*)(g_xln + (size_t)row * D))[lane] = o;
}

// ---------------- kernel 2: fp16 mma.sync GEMM (A resident, B 3-stage) ----------------
__device__ __forceinline__ void load_B_stage(__half* Bst, int tid, int idx) {
    int nb = (idx >> 3) * NTC, kb = (idx & 7) * KC;
    #pragma unroll
    for (int t = 0; t < 4; t++) {                  /* 1024 16B-chunks / 256 thr */
        int ch = tid + (t << 8);
        int row = ch >> 2, c8 = (ch & 3) * 8;      /* halves */
        cp_async16((char*)Bst + row * (B_STRH * 2) + c8 * 2,
                   g_WcatT + (size_t)(nb + row) * D + kb + c8);
    }
    asm volatile("cp.async.commit_group;\n");
}

__global__ __launch_bounds__(256, 1) void gemm_kernel() {
    extern __shared__ __align__(16) char smem[];
    __half* As = (__half*)smem;                          /* [MT][A_STRH] */
    __half* Bs = (__half*)(smem + SM_A_BYTES);           /* 3 x [NTC][B_STRH] */
    int tid = threadIdx.x;
    int mBase = blockIdx.x * MT;
    int warp = tid >> 5, lane = tid & 31;
    int wm = warp & 1, wn = warp >> 1;                   /* 64x64 warp tile */
    int g = lane >> 2, t = lane & 3;

    /* prologue: A tile (128x256 half) + B stage 0 = group 0; B stage 1 = group 1 */
    #pragma unroll
    for (int i = 0; i < 16; i++) {                       /* 4096 chunks */
        int ch = tid + (i << 8);
        int row = ch >> 5, c8 = (ch & 31) * 8;
        cp_async16((char*)As + row * (A_STRH * 2) + c8 * 2,
                   g_xln + (size_t)(mBase + row) * D + c8);
    }
    load_B_stage(Bs + 0 * NTC * B_STRH, tid, 0);         /* commits group 0 (A+B0) */
    load_B_stage(Bs + 1 * NTC * B_STRH, tid, 1);         /* group 1 */

    float c[4][8][4];
    for (int i = 0; i < NITER; i++) {
        int nc = i >> 3, kc = i & 7;
        if (kc == 0) {
            #pragma unroll
            for (int mi = 0; mi < 4; mi++)
                #pragma unroll
                for (int ni = 0; ni < 8; ni++)
                    #pragma unroll
                    for (int j = 0; j < 4; j++) c[mi][ni][j] = 0.f;
        }
        if (i < NITER - 2) asm volatile("cp.async.wait_group 1;\n" ::: "memory");
        else               asm volatile("cp.async.wait_group 0;\n" ::: "memory");
        __syncthreads();
        if (i + 2 < NITER)
            load_B_stage(Bs + ((i + 2) % 3) * NTC * B_STRH, tid, i + 2);

        const __half* Bst = Bs + (i % 3) * NTC * B_STRH;
        #pragma unroll
        for (int ks = 0; ks < 2; ks++) {
            unsigned af[4][4], bf[8][2];
            int kabs = kc * KC + ks * 16 + 2 * t;        /* A absolute col */
            int krel = ks * 16 + 2 * t;                  /* B stage-relative */
            #pragma unroll
            for (int mi = 0; mi < 4; mi++) {
                int rb = wm * 64 + mi * 16 + g;
                af[mi][0] = *(const unsigned*)(As + rb * A_STRH + kabs);
                af[mi][1] = *(const unsigned*)(As + (rb + 8) * A_STRH + kabs);
                af[mi][2] = *(const unsigned*)(As + rb * A_STRH + kabs + 8);
                af[mi][3] = *(const unsigned*)(As + (rb + 8) * A_STRH + kabs + 8);
            }
            #pragma unroll
            for (int ni = 0; ni < 8; ni++) {
                int nr = wn * 64 + ni * 8 + g;
                bf[ni][0] = *(const unsigned*)(Bst + nr * B_STRH + krel);
                bf[ni][1] = *(const unsigned*)(Bst + nr * B_STRH + krel + 8);
            }
            #pragma unroll
            for (int mi = 0; mi < 4; mi++)
                #pragma unroll
                for (int ni = 0; ni < 8; ni++)
                    mma16(c[mi][ni], af[mi], bf[ni]);
        }

        if (kc == 7) {          /* epilogue for this N chunk: bias + fp16 store */
            int nBase = nc * NTC;
            #pragma unroll
            for (int mi = 0; mi < 4; mi++)
                #pragma unroll
                for (int ni = 0; ni < 8; ni++) {
                    int r0 = mBase + wm * 64 + mi * 16 + g;
                    int c0 = nBase + wn * 64 + ni * 8 + 2 * t;
                    float b0v = g_bias[c0], b1v = g_bias[c0 + 1];
                    __half2 v0 = __floats2half2_rn(c[mi][ni][0] + b0v, c[mi][ni][1] + b1v);
                    __half2 v1 = __floats2half2_rn(c[mi][ni][2] + b0v, c[mi][ni][3] + b1v);
                    *(__half2*)(g_Y + (size_t)r0 * NCAT + c0)       = v0;
                    *(__half2*)(g_Y + (size_t)(r0 + 8) * NCAT + c0) = v1;
                }
        }
    }
}

// ---------------- kernel 3: gates + bucketed scatter + residual ----------------
__global__ __launch_bounds__(256) void edge_kernel(const float* __restrict__ h,
                                                   const int* __restrict__ srcI,
                                                   const int* __restrict__ dstI,
                                                   const float* __restrict__ W2,
                                                   const float* __restrict__ b2,
                                                   float* __restrict__ out) {
    __shared__ __half sV[NN * D];          /* 10.5 KB */
    __shared__ float  sGate[NE];
    __shared__ float  sW2[GH];
    __shared__ int sSrc[NE], sBS[NN + 1], sBE[NE];
    int b = blockIdx.x;
    int tid = threadIdx.x;
    if (tid < NE) { sSrc[tid] = srcI[tid]; sBE[tid] = g_bEdge[tid]; }
    if (tid >= 64 && tid < 64 + NN + 1) sBS[tid - 64] = g_bStart[tid - 64];
    for (int i = tid; i < GH; i += 256) sW2[i] = W2[i];
    const __half* Yb = g_Y + (size_t)b * NN * NCAT;
    for (int i = tid; i < NN * 32; i += 256) {           /* V part: 672 uint4 */
        int n = i >> 5, cc = i & 31;
        ((uint4*)sV)[i] = ((const uint4*)(Yb + n * NCAT))[cc];
    }
    __syncthreads();

    int warp = tid >> 5, lane = tid & 31;
    float b2v = b2[0];
    for (int e = warp; e < NE; e += 8) {
        int s = sSrc[e], dn = dstI[e];
        const uint4* A4 = (const uint4*)(Yb + s * NCAT + 256);
        const uint4* B4 = (const uint4*)(Yb + dn * NCAT + 768);
        float sum = 0.f;
        #pragma unroll
        for (int i = lane; i < 64; i += 32) {
            uint4 ua = __ldg(A4 + i), ub = __ldg(B4 + i);
            const float* wv = sW2 + i * 8;
            float2 a0 = __half22float2(*(__half2*)&ua.x), d0 = __half22float2(*(__half2*)&ub.x);
            float2 a1 = __half22float2(*(__half2*)&ua.y), d1 = __half22float2(*(__half2*)&ub.y);
            float2 a2 = __half22float2(*(__half2*)&ua.z), d2 = __half22float2(*(__half2*)&ub.z);
            float2 a3 = __half22float2(*(__half2*)&ua.w), d3 = __half22float2(*(__half2*)&ub.w);
            sum += gelu1(a0.x + d0.x) * wv[0] + gelu1(a0.y + d0.y) * wv[1];
            sum += gelu1(a1.x + d1.x) * wv[2] + gelu1(a1.y + d1.y) * wv[3];
            sum += gelu1(a2.x + d2.x) * wv[4] + gelu1(a2.y + d2.y) * wv[5];
            sum += gelu1(a3.x + d3.x) * wv[6] + gelu1(a3.y + d3.y) * wv[7];
        }
        #pragma unroll
        for (int off = 16; off; off >>= 1) sum += __shfl_xor_sync(0xffffffffu, sum, off);
        if (!lane) sGate[e] = 1.f / (1.f + __expf(-(sum + b2v)));
    }
    __syncthreads();

    const float* hb = h + (size_t)b * NN * D;
    float* ob = out + (size_t)b * NN * D;
    int col = tid & 63, sub = tid >> 6;
    for (int n0 = 0; n0 < 24; n0 += 4) {
        int n = n0 + sub;
        if (n < NN) {
            float4 acc = ((const float4*)(hb + n * D))[col];
            int jEnd = sBS[n + 1];
            for (int j = sBS[n]; j < jEnd; j++) {
                int e = sBE[j];
                float gte = sGate[e];
                uint2 u = *(const uint2*)(sV + sSrc[e] * D + col * 4);
                float2 lo = __half22float2(*(__half2*)&u.x);
                float2 hi = __half22float2(*(__half2*)&u.y);
                acc.x += gte * lo.x; acc.y += gte * lo.y;
                acc.z += gte * hi.x; acc.w += gte * hi.y;
            }
            ((float4*)(ob + n * D))[col] = acc;
        }
    }
}

// ---------------- launcher ----------------
extern "C" void kernel_launch(void* const* d_in, const int* in_sizes, int n_in,
                              void* d_out, int out_size) {
    const float* h    = (const float*)d_in[0];
    const int*   srcI = (const int*)d_in[1];
    const int*   dstI = (const int*)d_in[2];
    const float* ln_w = (const float*)d_in[3];
    const float* ln_b = (const float*)d_in[4];
    const float* Wv   = (const float*)d_in[5];
    const float* bv   = (const float*)d_in[6];
    const float* W1   = (const float*)d_in[7];
    const float* b1   = (const float*)d_in[8];
    const float* W2   = (const float*)d_in[9];
    const float* b2   = (const float*)d_in[10];
    float* out = (float*)d_out;

    cudaFuncSetAttribute(gemm_kernel, cudaFuncAttributeMaxDynamicSharedMemorySize, GEMM_SMEM);

    prep_kernel<<<(D * NCAT + 255) / 256, 256>>>(Wv, bv, W1, b1, srcI, dstI);
    ln_kernel<<<M_TOTAL / 8, 256>>>(h, ln_w, ln_b);
    gemm_kernel<<<M_TOTAL / MT, 256, GEMM_SMEM>>>();
    edge_kernel<<<NB, 256>>>(h, srcI, dstI, W2, b2, out);
}